// round 1
// baseline (speedup 1.0000x reference)
#include <cuda_runtime.h>

#define B_GRAPHS 4096
#define NN 32
#define DD 128
#define HH 2
#define HD 256   // H*D

// ---- shared memory layout (floats) ----
// xs : [32][128]            @ 0      (4096)
// qs : [32][260]            @ 4096   (8320)   (stride 260 = conflict-free f4)
// ks : [32][260]            @ 12416  (8320)
// vs : [32][260]            @ 20736  (8320)
// ws : [2][32][33]          @ 29056  (2112)   (scores, then sparsemax weights in place)
// po : [2][32][128]         @ 4096   (8192)   (aliases qs; q dead by then)
#define SMEM_FLOATS 31168
#define QS_STRIDE 260
#define WS_H 1056   // 32*33

__device__ __forceinline__ void project_col(const float* __restrict__ xs,
                                            const float* __restrict__ W,
                                            float* __restrict__ dst,
                                            int c)
{
    float acc[NN];
#pragma unroll
    for (int i = 0; i < NN; ++i) acc[i] = 0.f;

#pragma unroll 2
    for (int k4 = 0; k4 < DD / 4; ++k4) {
        const int kk = k4 * 4;
        const float w0 = W[(kk + 0) * HD + c];
        const float w1 = W[(kk + 1) * HD + c];
        const float w2 = W[(kk + 2) * HD + c];
        const float w3 = W[(kk + 3) * HD + c];
#pragma unroll
        for (int i = 0; i < NN; ++i) {
            const float4 xv = *(const float4*)&xs[i * DD + kk];
            float a = acc[i];
            a = fmaf(xv.x, w0, a);
            a = fmaf(xv.y, w1, a);
            a = fmaf(xv.z, w2, a);
            a = fmaf(xv.w, w3, a);
            acc[i] = a;
        }
    }
#pragma unroll
    for (int i = 0; i < NN; ++i) dst[i * QS_STRIDE + c] = acc[i];
}

__global__ __launch_bounds__(256, 1)
void attn_group_kernel(const float* __restrict__ x,
                       const float* __restrict__ WK,
                       const float* __restrict__ WV,
                       const float* __restrict__ WQ,
                       float* __restrict__ out,      // [B*N, D]
                       float* __restrict__ weight)   // [B*N, N, H]
{
    extern __shared__ float sm[];
    float* xs = sm;
    float* qs = sm + 4096;
    float* ks = sm + 12416;
    float* vs = sm + 20736;
    float* ws = sm + 29056;
    float* po = sm + 4096;   // alias qs

    const int b = blockIdx.x;
    const int t = threadIdx.x;

    // ---- load x tile [32][128] ----
    {
        const float4* xg = (const float4*)(x + (size_t)b * NN * DD);
        float4* xs4 = (float4*)xs;
#pragma unroll
        for (int r = 0; r < 4; ++r) xs4[t + 256 * r] = xg[t + 256 * r];
    }
    __syncthreads();

    // ---- Q,K,V projections: thread t owns column c = t of the 256 columns ----
    project_col(xs, WQ, qs, t);
    project_col(xs, WK, ks, t);
    project_col(xs, WV, vs, t);
    __syncthreads();

    // ---- scores: score[i][j][h] = q[i,h,:].k[j,h,:] / 16 ----
    {
        const int j  = t & 31;
        const int pg = t >> 5;          // 8 groups, each covers 4 i-rows x 2 heads
        float acc[4][2];
#pragma unroll
        for (int i4 = 0; i4 < 4; ++i4)
#pragma unroll
            for (int h = 0; h < 2; ++h) acc[i4][h] = 0.f;

#pragma unroll
        for (int h = 0; h < 2; ++h) {
            const float* krow = ks + j * QS_STRIDE + h * DD;
#pragma unroll
            for (int dc = 0; dc < 4; ++dc) {          // 4 chunks of 32 dims
                float4 kv[8];
#pragma unroll
                for (int u = 0; u < 8; ++u)
                    kv[u] = *(const float4*)&krow[dc * 32 + u * 4];
#pragma unroll
                for (int i4 = 0; i4 < 4; ++i4) {
                    const float* qrow = qs + (pg * 4 + i4) * QS_STRIDE + h * DD + dc * 32;
                    float a = acc[i4][h];
#pragma unroll
                    for (int u = 0; u < 8; ++u) {
                        const float4 qv = *(const float4*)&qrow[u * 4];
                        a = fmaf(qv.x, kv[u].x, a);
                        a = fmaf(qv.y, kv[u].y, a);
                        a = fmaf(qv.z, kv[u].z, a);
                        a = fmaf(qv.w, kv[u].w, a);
                    }
                    acc[i4][h] = a;
                }
            }
        }
        const float inv = 1.0f / 16.0f;   // 1/sqrt(D*H)
#pragma unroll
        for (int i4 = 0; i4 < 4; ++i4)
#pragma unroll
            for (int h = 0; h < 2; ++h)
                ws[h * WS_H + (pg * 4 + i4) * 33 + j] = acc[i4][h] * inv;
    }
    __syncthreads();

    // ---- sparsemax over j for each (i,h): 64 independent problems of size 32 ----
    if (t < 64) {
        const int i = t >> 1;
        const int h = t & 1;
        float* zrow = ws + h * WS_H + i * 33;

        float zs[NN];
#pragma unroll
        for (int j = 0; j < NN; ++j) zs[j] = zrow[j];

        // odd-even transposition sort, descending, fully unrolled (registers)
#pragma unroll
        for (int pass = 0; pass < NN; ++pass) {
            const int start = pass & 1;
#pragma unroll
            for (int idx = 0; idx < NN - 1; ++idx) {
                if (((idx & 1) == start)) {
                    const float a = zs[idx];
                    const float c = zs[idx + 1];
                    zs[idx]     = fmaxf(a, c);
                    zs[idx + 1] = fminf(a, c);
                }
            }
        }

        float csum = 0.f, ssum = 0.f;
        int ksup = 0;
#pragma unroll
        for (int k = 1; k <= NN; ++k) {
            const float zk = zs[k - 1];
            csum += zk;
            if (1.0f + (float)k * zk > csum) { ksup += 1; ssum += zk; }
        }
        const float tau = (ssum - 1.0f) / (float)ksup;

#pragma unroll
        for (int j = 0; j < NN; ++j)
            zrow[j] = fmaxf(zrow[j] - tau, 0.f);
    }
    __syncthreads();

    // ---- write weight output: w[b,i,j,h] -> weight[((b*32+i)*32+j)*2+h] ----
    {
        float* wg = weight + (size_t)b * (NN * NN * HH);
#pragma unroll
        for (int r = 0; r < 8; ++r) {
            const int o = t + 256 * r;           // o = i*64 + j*2 + h
            const int i = o >> 6;
            const int j = (o >> 1) & 31;
            const int h = o & 1;
            wg[o] = ws[h * WS_H + i * 33 + j];
        }
    }

    // ---- out: po[h][i][d] = sum_j w[i,j,h] * v[j,h,d] ----
    {
        const int h = t >> 7;
        const int d = t & 127;
        float acc[NN];
#pragma unroll
        for (int i = 0; i < NN; ++i) acc[i] = 0.f;
#pragma unroll 4
        for (int j = 0; j < NN; ++j) {
            const float vv = vs[j * QS_STRIDE + h * DD + d];
#pragma unroll
            for (int i = 0; i < NN; ++i)
                acc[i] = fmaf(ws[h * WS_H + i * 33 + j], vv, acc[i]);
        }
#pragma unroll
        for (int i = 0; i < NN; ++i)
            po[h * 4096 + i * DD + d] = acc[i];
    }
    __syncthreads();

    // ---- combine heads (mean) and write output ----
    {
        float* og = out + (size_t)b * (NN * DD);
#pragma unroll
        for (int r = 0; r < 16; ++r) {
            const int o = t + 256 * r;
            og[o] = 0.5f * (po[o] + po[4096 + o]);
        }
    }
}

extern "C" void kernel_launch(void* const* d_in, const int* in_sizes, int n_in,
                              void* d_out, int out_size)
{
    (void)in_sizes; (void)n_in; (void)out_size;
    const float* x  = (const float*)d_in[0];
    const float* WK = (const float*)d_in[1];
    const float* WV = (const float*)d_in[2];
    const float* WQ = (const float*)d_in[3];

    float* out    = (float*)d_out;                       // [B*N, D]
    float* weight = out + (size_t)B_GRAPHS * NN * DD;    // [B*N, N, H]

    cudaFuncSetAttribute(attn_group_kernel,
                         cudaFuncAttributeMaxDynamicSharedMemorySize,
                         SMEM_FLOATS * sizeof(float));

    attn_group_kernel<<<B_GRAPHS, 256, SMEM_FLOATS * sizeof(float)>>>(
        x, WK, WV, WQ, out, weight);
}

// round 2
// speedup vs baseline: 1.0003x; 1.0003x over previous
#include <cuda_runtime.h>

#define B_GRAPHS 4096
#define NN 32
#define DD 128
#define HH 2
#define HD 256   // H*D

// ---- shared memory layout (floats) ----
// xs : [32][128]            @ 0      (4096)
// qs : [32][260]            @ 4096   (8320)   (stride 260 = conflict-free f4)
// ks : [32][260]            @ 12416  (8320)
// vs : [32][260]            @ 20736  (8320)
// ws : [2][32][33]          @ 29056  (2112)   (scores, then sparsemax weights in place)
// po : [2][32][128]         @ 4096   (8192)   (aliases qs; q dead by then)
#define SMEM_FLOATS 31168
#define QS_STRIDE 260
#define WS_H 1056   // 32*33

__device__ __forceinline__ void project_col(const float* __restrict__ xs,
                                            const float* __restrict__ W,
                                            float* __restrict__ dst,
                                            int c)
{
    float acc[NN];
#pragma unroll
    for (int i = 0; i < NN; ++i) acc[i] = 0.f;

#pragma unroll 2
    for (int k4 = 0; k4 < DD / 4; ++k4) {
        const int kk = k4 * 4;
        const float w0 = W[(kk + 0) * HD + c];
        const float w1 = W[(kk + 1) * HD + c];
        const float w2 = W[(kk + 2) * HD + c];
        const float w3 = W[(kk + 3) * HD + c];
#pragma unroll
        for (int i = 0; i < NN; ++i) {
            const float4 xv = *(const float4*)&xs[i * DD + kk];
            float a = acc[i];
            a = fmaf(xv.x, w0, a);
            a = fmaf(xv.y, w1, a);
            a = fmaf(xv.z, w2, a);
            a = fmaf(xv.w, w3, a);
            acc[i] = a;
        }
    }
#pragma unroll
    for (int i = 0; i < NN; ++i) dst[i * QS_STRIDE + c] = acc[i];
}

__global__ __launch_bounds__(256, 1)
void attn_group_kernel(const float* __restrict__ x,
                       const float* __restrict__ WK,
                       const float* __restrict__ WV,
                       const float* __restrict__ WQ,
                       float* __restrict__ out,      // [B*N, D]
                       float* __restrict__ weight)   // [B*N, N, H]
{
    extern __shared__ float sm[];
    float* xs = sm;
    float* qs = sm + 4096;
    float* ks = sm + 12416;
    float* vs = sm + 20736;
    float* ws = sm + 29056;
    float* po = sm + 4096;   // alias qs

    const int b = blockIdx.x;
    const int t = threadIdx.x;

    // ---- load x tile [32][128] ----
    {
        const float4* xg = (const float4*)(x + (size_t)b * NN * DD);
        float4* xs4 = (float4*)xs;
#pragma unroll
        for (int r = 0; r < 4; ++r) xs4[t + 256 * r] = xg[t + 256 * r];
    }
    __syncthreads();

    // ---- Q,K,V projections: thread t owns column c = t of the 256 columns ----
    project_col(xs, WQ, qs, t);
    project_col(xs, WK, ks, t);
    project_col(xs, WV, vs, t);
    __syncthreads();

    // ---- scores: score[i][j][h] = q[i,h,:].k[j,h,:] / 16 ----
    {
        const int j  = t & 31;
        const int pg = t >> 5;          // 8 groups, each covers 4 i-rows x 2 heads
        float acc[4][2];
#pragma unroll
        for (int i4 = 0; i4 < 4; ++i4)
#pragma unroll
            for (int h = 0; h < 2; ++h) acc[i4][h] = 0.f;

#pragma unroll
        for (int h = 0; h < 2; ++h) {
            const float* krow = ks + j * QS_STRIDE + h * DD;
#pragma unroll
            for (int dc = 0; dc < 4; ++dc) {          // 4 chunks of 32 dims
                float4 kv[8];
#pragma unroll
                for (int u = 0; u < 8; ++u)
                    kv[u] = *(const float4*)&krow[dc * 32 + u * 4];
#pragma unroll
                for (int i4 = 0; i4 < 4; ++i4) {
                    const float* qrow = qs + (pg * 4 + i4) * QS_STRIDE + h * DD + dc * 32;
                    float a = acc[i4][h];
#pragma unroll
                    for (int u = 0; u < 8; ++u) {
                        const float4 qv = *(const float4*)&qrow[u * 4];
                        a = fmaf(qv.x, kv[u].x, a);
                        a = fmaf(qv.y, kv[u].y, a);
                        a = fmaf(qv.z, kv[u].z, a);
                        a = fmaf(qv.w, kv[u].w, a);
                    }
                    acc[i4][h] = a;
                }
            }
        }
        const float inv = 1.0f / 16.0f;   // 1/sqrt(D*H)
#pragma unroll
        for (int i4 = 0; i4 < 4; ++i4)
#pragma unroll
            for (int h = 0; h < 2; ++h)
                ws[h * WS_H + (pg * 4 + i4) * 33 + j] = acc[i4][h] * inv;
    }
    __syncthreads();

    // ---- sparsemax over j for each (i,h): 64 independent problems of size 32 ----
    if (t < 64) {
        const int i = t >> 1;
        const int h = t & 1;
        float* zrow = ws + h * WS_H + i * 33;

        float zs[NN];
#pragma unroll
        for (int j = 0; j < NN; ++j) zs[j] = zrow[j];

        // odd-even transposition sort, descending, fully unrolled (registers)
#pragma unroll
        for (int pass = 0; pass < NN; ++pass) {
            const int start = pass & 1;
#pragma unroll
            for (int idx = 0; idx < NN - 1; ++idx) {
                if (((idx & 1) == start)) {
                    const float a = zs[idx];
                    const float c = zs[idx + 1];
                    zs[idx]     = fmaxf(a, c);
                    zs[idx + 1] = fminf(a, c);
                }
            }
        }

        float csum = 0.f, ssum = 0.f;
        int ksup = 0;
#pragma unroll
        for (int k = 1; k <= NN; ++k) {
            const float zk = zs[k - 1];
            csum += zk;
            if (1.0f + (float)k * zk > csum) { ksup += 1; ssum += zk; }
        }
        const float tau = (ssum - 1.0f) / (float)ksup;

#pragma unroll
        for (int j = 0; j < NN; ++j)
            zrow[j] = fmaxf(zrow[j] - tau, 0.f);
    }
    __syncthreads();

    // ---- write weight output: w[b,i,j,h] -> weight[((b*32+i)*32+j)*2+h] ----
    {
        float* wg = weight + (size_t)b * (NN * NN * HH);
#pragma unroll
        for (int r = 0; r < 8; ++r) {
            const int o = t + 256 * r;           // o = i*64 + j*2 + h
            const int i = o >> 6;
            const int j = (o >> 1) & 31;
            const int h = o & 1;
            wg[o] = ws[h * WS_H + i * 33 + j];
        }
    }

    // ---- out: po[h][i][d] = sum_j w[i,j,h] * v[j,h,d] ----
    {
        const int h = t >> 7;
        const int d = t & 127;
        float acc[NN];
#pragma unroll
        for (int i = 0; i < NN; ++i) acc[i] = 0.f;
#pragma unroll 4
        for (int j = 0; j < NN; ++j) {
            const float vv = vs[j * QS_STRIDE + h * DD + d];
#pragma unroll
            for (int i = 0; i < NN; ++i)
                acc[i] = fmaf(ws[h * WS_H + i * 33 + j], vv, acc[i]);
        }
#pragma unroll
        for (int i = 0; i < NN; ++i)
            po[h * 4096 + i * DD + d] = acc[i];
    }
    __syncthreads();

    // ---- combine heads (mean) and write output ----
    {
        float* og = out + (size_t)b * (NN * DD);
#pragma unroll
        for (int r = 0; r < 16; ++r) {
            const int o = t + 256 * r;
            og[o] = 0.5f * (po[o] + po[4096 + o]);
        }
    }
}

extern "C" void kernel_launch(void* const* d_in, const int* in_sizes, int n_in,
                              void* d_out, int out_size)
{
    (void)in_sizes; (void)n_in; (void)out_size;
    const float* x  = (const float*)d_in[0];
    const float* WK = (const float*)d_in[1];
    const float* WV = (const float*)d_in[2];
    const float* WQ = (const float*)d_in[3];

    float* out    = (float*)d_out;                       // [B*N, D]
    float* weight = out + (size_t)B_GRAPHS * NN * DD;    // [B*N, N, H]

    cudaFuncSetAttribute(attn_group_kernel,
                         cudaFuncAttributeMaxDynamicSharedMemorySize,
                         SMEM_FLOATS * sizeof(float));

    attn_group_kernel<<<B_GRAPHS, 256, SMEM_FLOATS * sizeof(float)>>>(
        x, WK, WV, WQ, out, weight);
}

// round 9
// speedup vs baseline: 3.1692x; 3.1683x over previous
#include <cuda_runtime.h>
#include <cuda_bf16.h>

#define THREADS 256
#define NBLK 1024

// ---- smem byte offsets ----
#define XHI 0u            // X hi  [128][128] bf16, rowbytes 256, swizzled   (32KB)
#define XLO 32768u        // X lo                                            (32KB)
#define STGH 65536u       // stage hi [128][256] bf16, rowbytes 512, swz     (64KB)  T then V
#define STGL 131072u      // stage lo                                        (64KB)
#define SCOR 196608u      // scores/weights fp32 [256][34]                   (34816B)
#define SMEM_BYTES 231424u
#define SC_STRIDE 34

// precomputed B^T: rows n in [0,256): WV col n; n in [256,512): A_h rows (h=(n-256)/128, k2=(n-256)%128)
__device__ __align__(16) __nv_bfloat16 g_whi[512 * 128];
__device__ __align__(16) __nv_bfloat16 g_wlo[512 * 128];

// ================= prep kernel =================
__global__ void prep_w(const float* __restrict__ WQ, const float* __restrict__ WK,
                       const float* __restrict__ WV)
{
    const int n = blockIdx.x, k1 = threadIdx.x;
    __shared__ float wk[128];
    float val;
    if (n < 256) {
        val = WV[k1 * 256 + n];
    } else {
        const int h = (n - 256) >> 7, k2 = (n - 256) & 127;
        wk[k1] = WK[k2 * 256 + h * 128 + k1];
        __syncthreads();
        const float* wq = WQ + k1 * 256 + h * 128;
        float acc = 0.f;
#pragma unroll 8
        for (int e = 0; e < 128; ++e) acc = fmaf(wq[e], wk[e], acc);
        val = acc * 0.0625f;       // fold 1/sqrt(D*H)
    }
    __nv_bfloat16 hi = __float2bfloat16(val);
    g_whi[n * 128 + k1] = hi;
    g_wlo[n * 128 + k1] = __float2bfloat16(val - __bfloat162float(hi));
}

// ================= helpers =================
__device__ __forceinline__ unsigned swz(int r, unsigned off) {
    return off ^ (((unsigned)r & 7u) << 4);
}
__device__ __forceinline__ unsigned ldsm(const unsigned char* smp, unsigned base, int r, int c, int rb) {
    return *(const unsigned*)(smp + base + swz(r, (unsigned)(r * rb + c * 2)));
}
__device__ __forceinline__ void stsm(unsigned char* smp, unsigned base, int r, int c, int rb, unsigned v) {
    *(unsigned*)(smp + base + swz(r, (unsigned)(r * rb + c * 2))) = v;
}
__device__ __forceinline__ unsigned short lds16(const unsigned char* smp, unsigned base, int r, int c, int rb) {
    return *(const unsigned short*)(smp + base + swz(r, (unsigned)(r * rb + c * 2)));
}
__device__ __forceinline__ void split2(float a, float b, unsigned& hi, unsigned& lo) {
    __nv_bfloat16 ha = __float2bfloat16(a), hb = __float2bfloat16(b);
    float la = a - __bfloat162float(ha), lb = b - __bfloat162float(hb);
    __nv_bfloat16 lA = __float2bfloat16(la), lB = __float2bfloat16(lb);
    hi = ((unsigned)__bfloat16_as_ushort(hb) << 16) | (unsigned)__bfloat16_as_ushort(ha);
    lo = ((unsigned)__bfloat16_as_ushort(lB) << 16) | (unsigned)__bfloat16_as_ushort(lA);
}
__device__ __forceinline__ void mma_bf(float* d, const unsigned* a, const unsigned* b) {
    asm volatile(
        "mma.sync.aligned.m16n8k16.row.col.f32.bf16.bf16.f32 "
        "{%0,%1,%2,%3}, {%4,%5,%6,%7}, {%8,%9}, {%0,%1,%2,%3};\n"
        : "+f"(d[0]), "+f"(d[1]), "+f"(d[2]), "+f"(d[3])
        : "r"(a[0]), "r"(a[1]), "r"(a[2]), "r"(a[3]), "r"(b[0]), "r"(b[1]));
}

// projection GEMM: Y[:, warp cols] = X(128x128) * Wbig(128 x 512) slice; 3-pass bf16; stage to STG
__device__ __forceinline__ void proj_gemm(unsigned char* smp, int nbase, int scol, int grp, int q)
{
#pragma unroll
    for (int nc = 0; nc < 2; ++nc) {
        float D[2][8][4];
#pragma unroll
        for (int nt = 0; nt < 2; ++nt)
#pragma unroll
            for (int m = 0; m < 8; ++m)
#pragma unroll
                for (int e = 0; e < 4; ++e) D[nt][m][e] = 0.f;

        unsigned bh[2][2], bl[2][2];
#pragma unroll
        for (int nt = 0; nt < 2; ++nt) {
            const int n = nbase + nc * 16 + nt * 8 + grp;
            const unsigned short* ph = (const unsigned short*)g_whi + n * 128 + 2 * q;
            const unsigned short* pl = (const unsigned short*)g_wlo + n * 128 + 2 * q;
            bh[nt][0] = *(const unsigned*)ph;  bh[nt][1] = *(const unsigned*)(ph + 8);
            bl[nt][0] = *(const unsigned*)pl;  bl[nt][1] = *(const unsigned*)(pl + 8);
        }

#pragma unroll
        for (int kt = 0; kt < 8; ++kt) {
            unsigned bh2[2][2], bl2[2][2];
            if (kt < 7) {
#pragma unroll
                for (int nt = 0; nt < 2; ++nt) {
                    const int n = nbase + nc * 16 + nt * 8 + grp;
                    const unsigned short* ph = (const unsigned short*)g_whi + n * 128 + (kt + 1) * 16 + 2 * q;
                    const unsigned short* pl = (const unsigned short*)g_wlo + n * 128 + (kt + 1) * 16 + 2 * q;
                    bh2[nt][0] = *(const unsigned*)ph;  bh2[nt][1] = *(const unsigned*)(ph + 8);
                    bl2[nt][0] = *(const unsigned*)pl;  bl2[nt][1] = *(const unsigned*)(pl + 8);
                }
            }
            unsigned A[8][4];
            const int c0 = kt * 16 + 2 * q;
#pragma unroll
            for (int m = 0; m < 8; ++m) {
                const int r0 = m * 16 + grp;
                A[m][0] = ldsm(smp, XHI, r0,     c0,     256);
                A[m][1] = ldsm(smp, XHI, r0 + 8, c0,     256);
                A[m][2] = ldsm(smp, XHI, r0,     c0 + 8, 256);
                A[m][3] = ldsm(smp, XHI, r0 + 8, c0 + 8, 256);
            }
#pragma unroll
            for (int nt = 0; nt < 2; ++nt)
#pragma unroll
                for (int m = 0; m < 8; ++m) mma_bf(D[nt][m], A[m], bh[nt]);
#pragma unroll
            for (int nt = 0; nt < 2; ++nt)
#pragma unroll
                for (int m = 0; m < 8; ++m) mma_bf(D[nt][m], A[m], bl[nt]);
#pragma unroll
            for (int m = 0; m < 8; ++m) {
                const int r0 = m * 16 + grp;
                A[m][0] = ldsm(smp, XLO, r0,     c0,     256);
                A[m][1] = ldsm(smp, XLO, r0 + 8, c0,     256);
                A[m][2] = ldsm(smp, XLO, r0,     c0 + 8, 256);
                A[m][3] = ldsm(smp, XLO, r0 + 8, c0 + 8, 256);
            }
#pragma unroll
            for (int nt = 0; nt < 2; ++nt)
#pragma unroll
                for (int m = 0; m < 8; ++m) mma_bf(D[nt][m], A[m], bh[nt]);
#pragma unroll
            for (int nt = 0; nt < 2; ++nt)
#pragma unroll
                for (int u = 0; u < 2; ++u) {
                    bh[nt][u] = bh2[nt][u];
                    bl[nt][u] = bl2[nt][u];
                }
        }
        // stage (split hi/lo)
#pragma unroll
        for (int nt = 0; nt < 2; ++nt)
#pragma unroll
            for (int m = 0; m < 8; ++m) {
                const int r0 = m * 16 + grp;
                const int c = scol + nc * 16 + nt * 8 + 2 * q;
                unsigned hi, lo;
                split2(D[nt][m][0], D[nt][m][1], hi, lo);
                stsm(smp, STGH, r0, c, 512, hi);
                stsm(smp, STGL, r0, c, 512, lo);
                split2(D[nt][m][2], D[nt][m][3], hi, lo);
                stsm(smp, STGH, r0 + 8, c, 512, hi);
                stsm(smp, STGL, r0 + 8, c, 512, lo);
            }
    }
}

// ================= main kernel: 1 CTA = 4 graphs =================
__global__ __launch_bounds__(THREADS, 1)
void attn_hmma(const float* __restrict__ x,
               float* __restrict__ out,      // [B*N, 128]
               float* __restrict__ weight)   // [B*N, 32, 2]
{
    extern __shared__ unsigned char smp[];
    const int t = threadIdx.x;
    const int w = t >> 5, lane = t & 31, grp = lane >> 2, q = lane & 3;

    // ---- load X, split hi/lo ----
    {
        const float2* xg = (const float2*)(x + (size_t)blockIdx.x * 16384);
#pragma unroll
        for (int it = 0; it < 32; ++it) {
            const int e2 = t + 256 * it;
            const float2 v = xg[e2];
            const int r = e2 >> 6, c = (e2 & 63) * 2;
            unsigned hi, lo;
            split2(v.x, v.y, hi, lo);
            stsm(smp, XHI, r, c, 256, hi);
            stsm(smp, XLO, r, c, 256, lo);
        }
    }
    __syncthreads();

    // ---- phase T: T = X * A_h^T (cols 256..511 of Wbig), staged [128][256] (h,k2) ----
    proj_gemm(smp, 256 + w * 32, w * 32, grp, q);
    __syncthreads();

    // ---- phase S: warp (g, h): S_gh[32x32] = T_gh * X_g^T ----
    {
        const int g = w >> 1, h = w & 1;
        float D[4][2][4];
#pragma unroll
        for (int nt = 0; nt < 4; ++nt)
#pragma unroll
            for (int m = 0; m < 2; ++m)
#pragma unroll
                for (int e = 0; e < 4; ++e) D[nt][m][e] = 0.f;

#pragma unroll
        for (int kt = 0; kt < 8; ++kt) {
            const int K0 = h * 128 + kt * 16 + 2 * q;
            unsigned Ah[2][4], Al[2][4];
#pragma unroll
            for (int m = 0; m < 2; ++m) {
                const int r0 = g * 32 + m * 16 + grp;
                Ah[m][0] = ldsm(smp, STGH, r0,     K0,     512);
                Ah[m][1] = ldsm(smp, STGH, r0 + 8, K0,     512);
                Ah[m][2] = ldsm(smp, STGH, r0,     K0 + 8, 512);
                Ah[m][3] = ldsm(smp, STGH, r0 + 8, K0 + 8, 512);
                Al[m][0] = ldsm(smp, STGL, r0,     K0,     512);
                Al[m][1] = ldsm(smp, STGL, r0 + 8, K0,     512);
                Al[m][2] = ldsm(smp, STGL, r0,     K0 + 8, 512);
                Al[m][3] = ldsm(smp, STGL, r0 + 8, K0 + 8, 512);
            }
#pragma unroll
            for (int nt = 0; nt < 4; ++nt) {
                const int rn = g * 32 + nt * 8 + grp;
                const int ck = kt * 16 + 2 * q;
                unsigned Bh[2], Bl[2];
                Bh[0] = ldsm(smp, XHI, rn, ck,     256);
                Bh[1] = ldsm(smp, XHI, rn, ck + 8, 256);
                Bl[0] = ldsm(smp, XLO, rn, ck,     256);
                Bl[1] = ldsm(smp, XLO, rn, ck + 8, 256);
#pragma unroll
                for (int m = 0; m < 2; ++m) {
                    mma_bf(D[nt][m], Ah[m], Bh);
                    mma_bf(D[nt][m], Al[m], Bh);
                    mma_bf(D[nt][m], Ah[m], Bl);
                }
            }
        }
        // stage scores fp32
        float* sc = (float*)(smp + SCOR);
#pragma unroll
        for (int nt = 0; nt < 4; ++nt)
#pragma unroll
            for (int m = 0; m < 2; ++m) {
                const int i0 = m * 16 + grp;
                const int p = g * 64 + h * 32 + i0;
                const int j = nt * 8 + 2 * q;
                float2 v0; v0.x = D[nt][m][0]; v0.y = D[nt][m][1];
                float2 v1; v1.x = D[nt][m][2]; v1.y = D[nt][m][3];
                *(float2*)&sc[p * SC_STRIDE + j] = v0;
                *(float2*)&sc[(p + 8) * SC_STRIDE + j] = v1;
            }
    }
    __syncthreads();

    // ---- sparsemax: thread t owns problem p = t (g,h,i); in-place ----
    {
        float* zrow = (float*)(smp + SCOR) + t * SC_STRIDE;
        float z[32], s[32];
#pragma unroll
        for (int j = 0; j < 32; ++j) { z[j] = zrow[j]; s[j] = z[j]; }
#pragma unroll
        for (int pass = 0; pass < 32; ++pass) {
            const int st = pass & 1;
#pragma unroll
            for (int idx = 0; idx < 31; ++idx) {
                if ((idx & 1) == st) {
                    const float a = s[idx], b = s[idx + 1];
                    s[idx] = fmaxf(a, b); s[idx + 1] = fminf(a, b);
                }
            }
        }
        float csum = 0.f, ssum = 0.f; int ksup = 0;
#pragma unroll
        for (int kk = 1; kk <= 32; ++kk) {
            const float zk = s[kk - 1];
            csum += zk;
            if (1.0f + (float)kk * zk > csum) { ksup += 1; ssum += zk; }
        }
        const float tau = (ssum - 1.0f) / (float)ksup;
#pragma unroll
        for (int j = 0; j < 32; ++j) zrow[j] = fmaxf(z[j] - tau, 0.f);
    }
    __syncthreads();

    // ---- weight -> gmem ----
    {
        float2* wg = (float2*)(weight + (size_t)blockIdx.x * 8192);
        const float* sc = (const float*)(smp + SCOR);
#pragma unroll
        for (int it = 0; it < 16; ++it) {
            const int idx = t + 256 * it;       // (gi, j)
            const int gi = idx >> 5, j = idx & 31;
            const int g = gi >> 5, i = gi & 31;
            float2 o;
            o.x = sc[(g * 64 + i) * SC_STRIDE + j];
            o.y = sc[(g * 64 + 32 + i) * SC_STRIDE + j];
            wg[idx] = o;
        }
    }

    // ---- phase V: V = X * WV (cols 0..255), staged into STG (T dead) ----
    proj_gemm(smp, w * 32, w * 32, grp, q);
    __syncthreads();

    // ---- phase O: warp (g, dhalf): O_g[32 x 64] = (0.5*w) * V, both heads in K=64 ----
    {
        const int g = w >> 1, dh = w & 1;
        const float* sc = (const float*)(smp + SCOR);
        float D[8][2][4];
#pragma unroll
        for (int n = 0; n < 8; ++n)
#pragma unroll
            for (int m = 0; m < 2; ++m)
#pragma unroll
                for (int e = 0; e < 4; ++e) D[n][m][e] = 0.f;

#pragma unroll
        for (int kt = 0; kt < 4; ++kt) {
            const int h = kt >> 1;
            const int jj = (kt * 16 + 2 * q) & 31;
            unsigned Ah[2][4], Al[2][4];
#pragma unroll
            for (int m = 0; m < 2; ++m) {
                const int p0 = g * 64 + h * 32 + m * 16 + grp;
                const float2 f0 = *(const float2*)&sc[p0 * SC_STRIDE + jj];
                const float2 f1 = *(const float2*)&sc[(p0 + 8) * SC_STRIDE + jj];
                const float2 f2 = *(const float2*)&sc[p0 * SC_STRIDE + jj + 8];
                const float2 f3 = *(const float2*)&sc[(p0 + 8) * SC_STRIDE + jj + 8];
                split2(0.5f * f0.x, 0.5f * f0.y, Ah[m][0], Al[m][0]);
                split2(0.5f * f1.x, 0.5f * f1.y, Ah[m][1], Al[m][1]);
                split2(0.5f * f2.x, 0.5f * f2.y, Ah[m][2], Al[m][2]);
                split2(0.5f * f3.x, 0.5f * f3.y, Ah[m][3], Al[m][3]);
            }
#pragma unroll
            for (int n = 0; n < 8; ++n) {
                const int cV = h * 128 + dh * 64 + n * 8 + grp;
                const int rb = g * 32 + jj;
                unsigned Bh[2], Bl[2];
                {
                    unsigned short a0 = lds16(smp, STGH, rb,     cV, 512);
                    unsigned short a1 = lds16(smp, STGH, rb + 1, cV, 512);
                    unsigned short a2 = lds16(smp, STGH, rb + 8, cV, 512);
                    unsigned short a3 = lds16(smp, STGH, rb + 9, cV, 512);
                    Bh[0] = (unsigned)a0 | ((unsigned)a1 << 16);
                    Bh[1] = (unsigned)a2 | ((unsigned)a3 << 16);
                    unsigned short b0 = lds16(smp, STGL, rb,     cV, 512);
                    unsigned short b1 = lds16(smp, STGL, rb + 1, cV, 512);
                    unsigned short b2 = lds16(smp, STGL, rb + 8, cV, 512);
                    unsigned short b3 = lds16(smp, STGL, rb + 9, cV, 512);
                    Bl[0] = (unsigned)b0 | ((unsigned)b1 << 16);
                    Bl[1] = (unsigned)b2 | ((unsigned)b3 << 16);
                }
#pragma unroll
                for (int m = 0; m < 2; ++m) {
                    mma_bf(D[n][m], Ah[m], Bh);
                    mma_bf(D[n][m], Al[m], Bh);
                    mma_bf(D[n][m], Ah[m], Bl);
                }
            }
        }
        // out write
#pragma unroll
        for (int n = 0; n < 8; ++n)
#pragma unroll
            for (int m = 0; m < 2; ++m) {
                const int i = m * 16 + grp;
                const int d = dh * 64 + n * 8 + 2 * q;
                const size_t row = ((size_t)blockIdx.x * 4 + g) * 32 + i;
                float2 v0; v0.x = D[n][m][0]; v0.y = D[n][m][1];
                float2 v1; v1.x = D[n][m][2]; v1.y = D[n][m][3];
                *(float2*)&out[row * 128 + d] = v0;
                *(float2*)&out[(row + 8) * 128 + d] = v1;
            }
    }
}

extern "C" void kernel_launch(void* const* d_in, const int* in_sizes, int n_in,
                              void* d_out, int out_size)
{
    (void)in_sizes; (void)n_in; (void)out_size;
    const float* x  = (const float*)d_in[0];
    const float* WK = (const float*)d_in[1];
    const float* WV = (const float*)d_in[2];
    const float* WQ = (const float*)d_in[3];

    float* out    = (float*)d_out;
    float* weight = out + (size_t)4096 * 32 * 128;

    prep_w<<<512, 128>>>(WQ, WK, WV);

    cudaFuncSetAttribute(attn_hmma, cudaFuncAttributeMaxDynamicSharedMemorySize, SMEM_BYTES);
    attn_hmma<<<NBLK, THREADS, SMEM_BYTES>>>(x, out, weight);
}